// round 12
// baseline (speedup 1.0000x reference)
#include <cuda_runtime.h>
#include <cstdint>

// Capsule routing. x:[128,2048,8] W:[32,2048,16,8] out:[128,32,16]
// R12: pass0 = mma.sync tf32 GEMM (R11, unchanged). pass1 = software-pipelined
// softmax: phaseA(n+1) [u_hat+logit+exp+shfl] overlaps phaseB(n) [c + s accum].
// Identity: b_k = (sum_{i<k} v_i) . u_hat  ->  u_hat/b never materialized.

#define BB 128
#define NN 2048
#define DD 8
#define JJ 32
#define PP 16
#define TPB 128
#define NNT0 64

// pass1 pipelined: b-tile 8 (r=2), NC=128, grid 16*16=256 (one wave @2 CTA/SM)
#define NC1P  128
#define NNT1P 16
#define NBT1P 16
#define WJS   132
#define WBUF  (JJ * WJS)               // 4224 floats per W stage
#define XS_OFF (2 * WBUF)              // 8448
#define ESH_OFF (XS_OFF + NC1P * 64)   // 8448 + 8192 = 16640
#define SMEM1P_B ((ESH_OFF + 64) * 4)  // 66816 B

// pass0 mma smem: rows padded to 44 floats (176B)
#define RS    44
#define AS_F  (128 * RS)
#define BS_F  (256 * RS)
#define BUF_F (AS_F + BS_F)
#define SMEM0_B (2 * BUF_F * 4)        // 135168 B

typedef unsigned long long u64;

__device__ __forceinline__ u64 fma2(u64 a, u64 b, u64 c) {
    u64 d; asm("fma.rn.f32x2 %0, %1, %2, %3;" : "=l"(d) : "l"(a), "l"(b), "l"(c));
    return d;
}
__device__ __forceinline__ u64 mul2(u64 a, u64 b) {
    u64 d; asm("mul.rn.f32x2 %0, %1, %2;" : "=l"(d) : "l"(a), "l"(b));
    return d;
}
__device__ __forceinline__ float lohi_add(u64 v) {
    float a, b; asm("mov.b64 {%0, %1}, %2;" : "=f"(a), "=f"(b) : "l"(v));
    return a + b;
}
__device__ __forceinline__ unsigned smem_u32(const void* p) {
    return (unsigned)__cvta_generic_to_shared(p);
}
__device__ __forceinline__ void cp16(unsigned dst, const void* src) {
    asm volatile("cp.async.cg.shared.global [%0], [%1], 16;" :: "r"(dst), "l"(src));
}
__device__ __forceinline__ void cp_commit() { asm volatile("cp.async.commit_group;"); }
__device__ __forceinline__ void cp_wait1()  { asm volatile("cp.async.wait_group 1;"); }
__device__ __forceinline__ void cp_wait0()  { asm volatile("cp.async.wait_group 0;"); }
__device__ __forceinline__ uint32_t tf32(float v) {
    uint32_t t; asm("cvt.rna.tf32.f32 %0, %1;" : "=r"(t) : "f"(v));
    return t;
}
__device__ __forceinline__ void mma8(float* c, const uint32_t* a, const uint32_t* b) {
    asm volatile(
        "mma.sync.aligned.m16n8k8.row.col.f32.tf32.tf32.f32 "
        "{%0,%1,%2,%3}, {%4,%5,%6,%7}, {%8,%9}, {%0,%1,%2,%3};"
        : "+f"(c[0]), "+f"(c[1]), "+f"(c[2]), "+f"(c[3])
        : "r"(a[0]), "r"(a[1]), "r"(a[2]), "r"(a[3]), "r"(b[0]), "r"(b[1]));
}

__device__ __align__(16) float g_part[(size_t)NNT0 * BB * JJ * PP];  // 16MB
__device__ __align__(16) float g_V[BB * JJ * PP];
__device__ float g_dummy;

__global__ void caps_dummy() { if (threadIdx.x == 0) g_dummy = 0.0f; }

// ============ pass0: mma.sync tf32 GEMM (R11, verified) ============
__global__ void __launch_bounds__(256, 1)
caps_pass0_mma(const float* __restrict__ xg, const float* __restrict__ Wg)
{
    extern __shared__ __align__(16) float sm[];
    const unsigned sm0 = smem_u32(sm);

    const int tid = threadIdx.x;
    const int w   = tid >> 5;
    const int lane = tid & 31;
    const int g   = lane >> 2;
    const int tig = lane & 3;
    const int jh  = blockIdx.x & 1;
    const int kt  = blockIdx.x >> 1;
    const int koff0 = kt * 256;

    auto stage = [&](int st) {
        const unsigned bufA = sm0 + (unsigned)((st & 1) * BUF_F) * 4;
        const unsigned bufB = bufA + (unsigned)AS_F * 4;
        const int koff = koff0 + st * 32;
        #pragma unroll
        for (int q = 0; q < 4; q++) {
            int c = tid + q * 256, b = c >> 3, h = c & 7;
            cp16(bufA + (unsigned)(b * RS + h * 4) * 4,
                 xg + (size_t)b * (NN * DD) + koff + h * 4);
        }
        #pragma unroll
        for (int q = 0; q < 8; q++) {
            int c = tid + q * 256, r = c >> 3, h = c & 7;
            int j = jh * 16 + (r >> 4), p = r & 15;
            int n = (koff >> 3) + (h >> 1);
            cp16(bufB + (unsigned)(r * RS + h * 4) * 4,
                 Wg + ((size_t)j * NN + n) * 128 + p * 8 + (h & 1) * 4);
        }
        cp_commit();
    };

    stage(0);

    float C[8][4][4];
    #pragma unroll
    for (int mt = 0; mt < 8; mt++)
        #pragma unroll
        for (int q = 0; q < 4; q++)
            #pragma unroll
            for (int e = 0; e < 4; e++) C[mt][q][e] = 0.0f;

    for (int st = 0; st < 8; st++) {
        cp_wait0();
        __syncthreads();
        if (st + 1 < 8) stage(st + 1);

        const float* As = sm + (st & 1) * BUF_F;
        const float* Bs = As + AS_F;

        #pragma unroll
        for (int kc = 0; kc < 4; kc++) {
            const int k0 = kc * 8 + tig;
            uint32_t Bf[4][2];
            #pragma unroll
            for (int q = 0; q < 4; q++) {
                const float* br = Bs + (w * 32 + q * 8 + g) * RS;
                Bf[q][0] = tf32(br[k0]);
                Bf[q][1] = tf32(br[k0 + 4]);
            }
            #pragma unroll
            for (int mt = 0; mt < 8; mt++) {
                const float* ar0 = As + (mt * 16 + g) * RS;
                const float* ar1 = ar0 + 8 * RS;
                uint32_t Af[4];
                Af[0] = tf32(ar0[k0]);
                Af[1] = tf32(ar1[k0]);
                Af[2] = tf32(ar0[k0 + 4]);
                Af[3] = tf32(ar1[k0 + 4]);
                #pragma unroll
                for (int q = 0; q < 4; q++) mma8(C[mt][q], Af, Bf[q]);
            }
        }
    }

    const float inv = 1.0f / 32.0f;
    #pragma unroll
    for (int mt = 0; mt < 8; mt++) {
        #pragma unroll
        for (int q = 0; q < 4; q++) {
            int jpg = jh * 256 + w * 32 + q * 8 + tig * 2;
            int j = jpg >> 4, p = jpg & 15;
            int b0 = mt * 16 + g;
            float* d0 = &g_part[(((size_t)kt * BB + b0) * JJ + j) * PP + p];
            float* d1 = &g_part[(((size_t)kt * BB + b0 + 8) * JJ + j) * PP + p];
            *reinterpret_cast<float2*>(d0) =
                make_float2(C[mt][q][0] * inv, C[mt][q][1] * inv);
            *reinterpret_cast<float2*>(d1) =
                make_float2(C[mt][q][2] * inv, C[mt][q][3] * inv);
        }
    }
}

// ============ pass1: software-pipelined routed pass ============
// phaseA(m): u_hat (into U), logit, exp, warp folds, e_sh[m&1] store.
// phaseB(m): read e_sh[m&1] sums, c = e/sum, s += c*U.
#define PHASEA(m, U, esave)                                               \
{                                                                         \
    const float* Wj = sm + ((m) & 1) * WBUF + j * WJS;                    \
    const float* xr = sm + XS_OFF + (m) * 64;                             \
    u64 X[2][4];                                                          \
    _Pragma("unroll")                                                     \
    for (int r = 0; r < 2; r++) {                                         \
        const ulonglong2* xp =                                            \
            reinterpret_cast<const ulonglong2*>(xr + (bp + 4*r) * 8);     \
        ulonglong2 t0 = xp[0], t1 = xp[1];                                \
        X[r][0] = t0.x; X[r][1] = t0.y; X[r][2] = t1.x; X[r][3] = t1.y;   \
    }                                                                     \
    _Pragma("unroll")                                                     \
    for (int p2 = 0; p2 < 8; p2++) {                                      \
        const ulonglong2* wr =                                            \
            reinterpret_cast<const ulonglong2*>(Wj + p2 * 16);            \
        ulonglong2 w0 = wr[0], w1 = wr[1], w2 = wr[2], w3 = wr[3];        \
        _Pragma("unroll")                                                 \
        for (int r = 0; r < 2; r++) {                                     \
            u64 a = mul2(w0.x, X[r][0]);                                  \
            a = fma2(w0.y, X[r][1], a);                                   \
            a = fma2(w1.x, X[r][2], a);                                   \
            a = fma2(w1.y, X[r][3], a);                                   \
            u64 b = mul2(w2.x, X[r][0]);                                  \
            b = fma2(w2.y, X[r][1], b);                                   \
            b = fma2(w3.x, X[r][2], b);                                   \
            b = fma2(w3.y, X[r][3], b);                                   \
            u64 pr; asm("mov.b64 %0, {%1, %2};" : "=l"(pr)                \
                        : "f"(lohi_add(a)), "f"(lohi_add(b)));            \
            U[r][p2] = pr;                                                \
        }                                                                 \
    }                                                                     \
    _Pragma("unroll")                                                     \
    for (int r = 0; r < 2; r++) {                                         \
        u64 la = mul2(V2[r][0], U[r][0]);                                 \
        u64 lb = mul2(V2[r][1], U[r][1]);                                 \
        la = fma2(V2[r][2], U[r][2], la);                                 \
        lb = fma2(V2[r][3], U[r][3], lb);                                 \
        la = fma2(V2[r][4], U[r][4], la);                                 \
        lb = fma2(V2[r][5], U[r][5], lb);                                 \
        la = fma2(V2[r][6], U[r][6], la);                                 \
        lb = fma2(V2[r][7], U[r][7], lb);                                 \
        float ev = __expf(lohi_add(la) + lohi_add(lb));                   \
        esave[r] = ev;                                                    \
        float v = ev;                                                     \
        v += __shfl_xor_sync(0xffffffffu, v, 4);                          \
        v += __shfl_xor_sync(0xffffffffu, v, 8);                          \
        v += __shfl_xor_sync(0xffffffffu, v, 16);                         \
        if (lane < 4) e_sh[((m) & 1) * 32 + (bp + 4*r) * 4 + w] = v;      \
    }                                                                     \
}

#define PHASEB(m, U, esave)                                               \
{                                                                         \
    _Pragma("unroll")                                                     \
    for (int r = 0; r < 2; r++) {                                         \
        float4 t = *reinterpret_cast<const float4*>(                      \
            &e_sh[((m) & 1) * 32 + (bp + 4*r) * 4]);                      \
        float c = esave[r] * __frcp_rn((t.x + t.y) + (t.z + t.w));        \
        u64 c2; asm("mov.b64 %0, {%1, %1};" : "=l"(c2) : "f"(c));         \
        _Pragma("unroll")                                                 \
        for (int q = 0; q < 8; q++)                                       \
            s2[r][q] = fma2(c2, U[r][q], s2[r][q]);                       \
    }                                                                     \
}

__global__ void __launch_bounds__(TPB, 2)
caps_pass1(const float* __restrict__ xg, const float* __restrict__ Wg)
{
    extern __shared__ __align__(16) float sm[];
    float* e_sh = sm + ESH_OFF;
    const unsigned sm0 = smem_u32(sm);

    const int tid  = threadIdx.x;
    const int bp   = tid & 3;
    const int j    = tid >> 2;
    const int lane = tid & 31;
    const int w    = tid >> 5;
    const int bt   = blockIdx.x & (NBT1P - 1);
    const int nt   = blockIdx.x >> 4;
    const int b0   = bt * 8;
    const int n0   = nt * NC1P;

    u64 V2[2][8];
    #pragma unroll
    for (int r = 0; r < 2; r++) {
        const ulonglong2* vp = reinterpret_cast<const ulonglong2*>(
            &g_V[((size_t)(b0 + bp + 4*r) * JJ + j) * PP]);
        #pragma unroll
        for (int q = 0; q < 4; q++) {
            ulonglong2 t = vp[q]; V2[r][2*q] = t.x; V2[r][2*q+1] = t.y;
        }
    }

    const int jb = tid >> 5, cc = tid & 31;
    const float* wbase = Wg + (size_t)jb * NN * 128 + cc * 4;

    auto stageW = [&](int st) {
        unsigned d = sm0 + (unsigned)((st & 1) * WBUF + jb * WJS + cc * 4) * 4;
        const float* s = wbase + (size_t)(n0 + st) * 128;
        #pragma unroll
        for (int q = 0; q < 8; q++)
            cp16(d + q * (4 * WJS * 4), s + (size_t)q * 4 * NN * 128);
    };

    // prologue: x preload (all NC1P n) + W stage 0 as group 0; W stage 1 group 1
    #pragma unroll
    for (int q = 0; q < 16; q++) {
        int c = tid + q * TPB;                  // 0..2047
        int n = c >> 4, b = (c >> 1) & 7, h = c & 1;
        cp16(sm0 + (unsigned)(XS_OFF + n * 64 + b * 8 + h * 4) * 4,
             xg + ((size_t)(b0 + b) * NN + (n0 + n)) * DD + h * 4);
    }
    stageW(0);
    cp_commit();
    stageW(1);
    cp_commit();

    u64 s2[2][8];
    #pragma unroll
    for (int r = 0; r < 2; r++)
        #pragma unroll
        for (int q = 0; q < 8; q++) s2[r][q] = 0ull;

    u64 uA[2][8], uB[2][8];
    float eA[2], eB[2];

    cp_wait1();                 // x + W0 landed
    __syncthreads();
    PHASEA(0, uA, eA);          // e_sh[0] written (visible after next bar)

    for (int nn = 0; nn < NC1P; nn += 2) {
        // even iteration nn
        cp_wait0();
        __syncthreads();
        if (nn + 2 < NC1P) { stageW(nn + 2); cp_commit(); }
        PHASEA(nn + 1, uB, eB);
        PHASEB(nn, uA, eA);
        // odd iteration nn+1
        cp_wait0();
        __syncthreads();
        if (nn + 3 < NC1P) { stageW(nn + 3); cp_commit(); }
        if (nn + 2 < NC1P) PHASEA(nn + 2, uA, eA);
        PHASEB(nn + 1, uB, eB);
    }

    #pragma unroll
    for (int r = 0; r < 2; r++) {
        ulonglong2* dst = reinterpret_cast<ulonglong2*>(
            &g_part[(((size_t)nt * BB + b0 + bp + 4*r) * JJ + j) * PP]);
        #pragma unroll
        for (int q = 0; q < 4; q++) {
            ulonglong2 t; t.x = s2[r][2*q]; t.y = s2[r][2*q+1]; dst[q] = t;
        }
    }
}

// ============ reduce over nt, squash, update V / write out ============
__global__ void caps_squash(float* __restrict__ outg, int stage, int nnt)
{
    int t    = blockIdx.x * blockDim.x + threadIdx.x;
    int quad = t & 3;
    int k    = (t >> 2) & 3;
    int vec  = t >> 4;
    if (vec >= BB * JJ) return;

    float4 acc = make_float4(0.f, 0.f, 0.f, 0.f);
    int cnt = nnt >> 2;
    for (int ntk = 0; ntk < cnt; ntk++) {
        int nt = k * cnt + ntk;
        float4 v = *reinterpret_cast<const float4*>(
            &g_part[((size_t)nt * BB * JJ + vec) * PP + quad * 4]);
        acc.x += v.x; acc.y += v.y; acc.z += v.z; acc.w += v.w;
    }
    #pragma unroll
    for (int m = 4; m <= 8; m <<= 1) {
        acc.x += __shfl_xor_sync(0xffffffffu, acc.x, m);
        acc.y += __shfl_xor_sync(0xffffffffu, acc.y, m);
        acc.z += __shfl_xor_sync(0xffffffffu, acc.z, m);
        acc.w += __shfl_xor_sync(0xffffffffu, acc.w, m);
    }

    float s2 = acc.x * acc.x + acc.y * acc.y + acc.z * acc.z + acc.w * acc.w;
    s2 += __shfl_xor_sync(0xffffffffu, s2, 1);
    s2 += __shfl_xor_sync(0xffffffffu, s2, 2);

    float scale = s2 / ((1.0f + s2) * sqrtf(s2 + 1e-7f));
    float4 v4 = make_float4(acc.x * scale, acc.y * scale,
                            acc.z * scale, acc.w * scale);

    if (k == 0) {
        if (stage == 2) {
            *reinterpret_cast<float4*>(&outg[vec * PP + quad * 4]) = v4;
        } else if (stage == 0) {
            *reinterpret_cast<float4*>(&g_V[vec * PP + quad * 4]) = v4;
        } else {
            float4 cur = *reinterpret_cast<const float4*>(&g_V[vec * PP + quad * 4]);
            cur.x += v4.x; cur.y += v4.y; cur.z += v4.z; cur.w += v4.w;
            *reinterpret_cast<float4*>(&g_V[vec * PP + quad * 4]) = cur;
        }
    }
}

extern "C" void kernel_launch(void* const* d_in, const int* in_sizes, int n_in,
                              void* d_out, int out_size)
{
    const float* x = (const float*)d_in[0];
    const float* W = (const float*)d_in[1];
    if (n_in >= 2 && in_sizes[0] > in_sizes[1]) {
        const float* tmp = x; x = W; W = tmp;
    }
    float* out = (float*)d_out;

    cudaFuncSetAttribute(caps_pass0_mma,
        cudaFuncAttributeMaxDynamicSharedMemorySize, SMEM0_B);
    cudaFuncSetAttribute(caps_pass1,
        cudaFuncAttributeMaxDynamicSharedMemorySize, SMEM1P_B);

    const int GRID1 = NBT1P * NNT1P;                        // 256
    const int SQ_BLOCK = 256;
    const int SQ_GRID  = (BB * JJ * 16 + SQ_BLOCK - 1) / SQ_BLOCK;

    caps_dummy<<<1, 32>>>();                                // 1 (slot 6 = pass1 #2)
    caps_pass0_mma<<<128, 256, SMEM0_B>>>(x, W);            // 2
    caps_squash<<<SQ_GRID, SQ_BLOCK>>>(out, 0, NNT0);       // 3: V = v0
    caps_pass1<<<GRID1, TPB, SMEM1P_B>>>(x, W);             // 4
    caps_squash<<<SQ_GRID, SQ_BLOCK>>>(out, 1, NNT1P);      // 5: V += v1
    caps_pass1<<<GRID1, TPB, SMEM1P_B>>>(x, W);             // 6 <- profiled
    caps_squash<<<SQ_GRID, SQ_BLOCK>>>(out, 2, NNT1P);      // 7: out
}

// round 13
// speedup vs baseline: 1.0944x; 1.0944x over previous
#include <cuda_runtime.h>
#include <cstdint>

// Capsule routing. x:[128,2048,8] W:[32,2048,16,8] out:[128,32,16]
// R13 = R11 (best: pass0 mma.sync tf32 GEMM + r=4 SIMT routed pass) with the
// dummy-launch overhead removed (5 -> 1, saves ~15us of timed graph) and a
// wider squash (k-split 8). R12's pipelined pass1 regressed (r=2 halved W
// reuse) and is reverted. Identity: b_k = (sum_{i<k} v_i) . u_hat.

#define BB 128
#define NN 2048
#define DD 8
#define JJ 32
#define PP 16
#define TPB 128
#define BT1  16
#define NC1  64
#define NBT1 8
#define NNT1 32
#define NNT0 64
#define WJS  132
#define WBUF (JJ * WJS)
#define XOFF (3 * WBUF)
#define X1F  (NC1 * BT1 * DD)
#define EOFF (XOFF + X1F)
#define SMEM1_B ((EOFF + 80) * 4)

// mma smem: rows padded to 44 floats (176B): conflict-free frag loads
#define RS    44
#define AS_F  (128 * RS)            // 5632 floats
#define BS_F  (256 * RS)            // 11264 floats
#define BUF_F (AS_F + BS_F)         // 16896
#define SMEM0_B (2 * BUF_F * 4)     // 135168 B

typedef unsigned long long u64;

__device__ __forceinline__ u64 fma2(u64 a, u64 b, u64 c) {
    u64 d; asm("fma.rn.f32x2 %0, %1, %2, %3;" : "=l"(d) : "l"(a), "l"(b), "l"(c));
    return d;
}
__device__ __forceinline__ u64 mul2(u64 a, u64 b) {
    u64 d; asm("mul.rn.f32x2 %0, %1, %2;" : "=l"(d) : "l"(a), "l"(b));
    return d;
}
__device__ __forceinline__ float lohi_add(u64 v) {
    float a, b; asm("mov.b64 {%0, %1}, %2;" : "=f"(a), "=f"(b) : "l"(v));
    return a + b;
}
__device__ __forceinline__ unsigned smem_u32(const void* p) {
    return (unsigned)__cvta_generic_to_shared(p);
}
__device__ __forceinline__ void cp16(unsigned dst, const void* src) {
    asm volatile("cp.async.cg.shared.global [%0], [%1], 16;" :: "r"(dst), "l"(src));
}
__device__ __forceinline__ void cp_commit() { asm volatile("cp.async.commit_group;"); }
__device__ __forceinline__ void cp_wait1()  { asm volatile("cp.async.wait_group 1;"); }
__device__ __forceinline__ void cp_wait0()  { asm volatile("cp.async.wait_group 0;"); }
__device__ __forceinline__ uint32_t tf32(float v) {
    uint32_t t; asm("cvt.rna.tf32.f32 %0, %1;" : "=r"(t) : "f"(v));
    return t;
}
__device__ __forceinline__ void mma8(float* c, const uint32_t* a, const uint32_t* b) {
    asm volatile(
        "mma.sync.aligned.m16n8k8.row.col.f32.tf32.tf32.f32 "
        "{%0,%1,%2,%3}, {%4,%5,%6,%7}, {%8,%9}, {%0,%1,%2,%3};"
        : "+f"(c[0]), "+f"(c[1]), "+f"(c[2]), "+f"(c[3])
        : "r"(a[0]), "r"(a[1]), "r"(a[2]), "r"(a[3]), "r"(b[0]), "r"(b[1]));
}

__device__ __align__(16) float g_part[(size_t)NNT0 * BB * JJ * PP];  // 16MB
__device__ __align__(16) float g_V[BB * JJ * PP];
__device__ float g_dummy;

__global__ void caps_dummy() { if (threadIdx.x == 0) g_dummy = 0.0f; }

// ============ pass0: mma.sync tf32 GEMM (R11, verified) ============
// D[b=128, jp=512] = x[128,K] @ Wrow[jp,K]^T, K=16384.
// grid 128: jh = bid&1 (256 jp cols), kt = bid>>1 (K-slice 256 = 32 n).
__global__ void __launch_bounds__(256, 1)
caps_pass0_mma(const float* __restrict__ xg, const float* __restrict__ Wg)
{
    extern __shared__ __align__(16) float sm[];
    const unsigned sm0 = smem_u32(sm);

    const int tid = threadIdx.x;
    const int w   = tid >> 5;
    const int lane = tid & 31;
    const int g   = lane >> 2;          // groupID
    const int tig = lane & 3;           // threadID in group
    const int jh  = blockIdx.x & 1;
    const int kt  = blockIdx.x >> 1;
    const int koff0 = kt * 256;

    auto stage = [&](int st) {
        const unsigned bufA = sm0 + (unsigned)((st & 1) * BUF_F) * 4;
        const unsigned bufB = bufA + (unsigned)AS_F * 4;
        const int koff = koff0 + st * 32;
        #pragma unroll
        for (int q = 0; q < 4; q++) {              // A: 1024 cp16
            int c = tid + q * 256, b = c >> 3, h = c & 7;
            cp16(bufA + (unsigned)(b * RS + h * 4) * 4,
                 xg + (size_t)b * (NN * DD) + koff + h * 4);
        }
        #pragma unroll
        for (int q = 0; q < 8; q++) {              // B: 2048 cp16
            int c = tid + q * 256, r = c >> 3, h = c & 7;
            int j = jh * 16 + (r >> 4), p = r & 15;
            int n = (koff >> 3) + (h >> 1);
            cp16(bufB + (unsigned)(r * RS + h * 4) * 4,
                 Wg + ((size_t)j * NN + n) * 128 + p * 8 + (h & 1) * 4);
        }
        cp_commit();
    };

    stage(0);

    float C[8][4][4];
    #pragma unroll
    for (int mt = 0; mt < 8; mt++)
        #pragma unroll
        for (int q = 0; q < 4; q++)
            #pragma unroll
            for (int e = 0; e < 4; e++) C[mt][q][e] = 0.0f;

    // distance-1 double buffer: wait stage st, bar, issue st+1, compute st.
    for (int st = 0; st < 8; st++) {
        cp_wait0();
        __syncthreads();
        if (st + 1 < 8) stage(st + 1);

        const float* As = sm + (st & 1) * BUF_F;
        const float* Bs = As + AS_F;

        #pragma unroll
        for (int kc = 0; kc < 4; kc++) {
            const int k0 = kc * 8 + tig;
            uint32_t Bf[4][2];
            #pragma unroll
            for (int q = 0; q < 4; q++) {
                const float* br = Bs + (w * 32 + q * 8 + g) * RS;
                Bf[q][0] = tf32(br[k0]);
                Bf[q][1] = tf32(br[k0 + 4]);
            }
            #pragma unroll
            for (int mt = 0; mt < 8; mt++) {
                const float* ar0 = As + (mt * 16 + g) * RS;
                const float* ar1 = ar0 + 8 * RS;
                uint32_t Af[4];
                Af[0] = tf32(ar0[k0]);
                Af[1] = tf32(ar1[k0]);
                Af[2] = tf32(ar0[k0 + 4]);
                Af[3] = tf32(ar1[k0 + 4]);
                #pragma unroll
                for (int q = 0; q < 4; q++) mma8(C[mt][q], Af, Bf[q]);
            }
        }
    }

    // epilogue: scale 1/32, write g_part[kt][b][j][p]
    const float inv = 1.0f / 32.0f;
    #pragma unroll
    for (int mt = 0; mt < 8; mt++) {
        #pragma unroll
        for (int q = 0; q < 4; q++) {
            int jpg = jh * 256 + w * 32 + q * 8 + tig * 2;
            int j = jpg >> 4, p = jpg & 15;
            int b0 = mt * 16 + g;
            float* d0 = &g_part[(((size_t)kt * BB + b0) * JJ + j) * PP + p];
            float* d1 = &g_part[(((size_t)kt * BB + b0 + 8) * JJ + j) * PP + p];
            *reinterpret_cast<float2*>(d0) =
                make_float2(C[mt][q][0] * inv, C[mt][q][1] * inv);
            *reinterpret_cast<float2*>(d1) =
                make_float2(C[mt][q][2] * inv, C[mt][q][3] * inv);
        }
    }
}

// ============ pass1: SIMT routed c = softmax_j(V.u_hat) (R6/R11) ============
__global__ void __launch_bounds__(TPB, 2)
caps_pass1(const float* __restrict__ xg, const float* __restrict__ Wg)
{
    extern __shared__ __align__(16) float sm[];
    float* e_sh = sm + EOFF;
    const unsigned sm0 = smem_u32(sm);

    const int tid  = threadIdx.x;
    const int bp   = tid & 3;
    const int j    = tid >> 2;
    const int lane = tid & 31;
    const int w    = tid >> 5;
    const int bt   = blockIdx.x & (NBT1 - 1);
    const int nt   = blockIdx.x >> 3;
    const int b0   = bt * BT1;
    const int n0   = nt * NC1;

    u64 V2[4][8];
    #pragma unroll
    for (int r = 0; r < 4; r++) {
        const ulonglong2* vp = reinterpret_cast<const ulonglong2*>(
            &g_V[((size_t)(b0 + bp + 4*r) * JJ + j) * PP]);
        #pragma unroll
        for (int q = 0; q < 4; q++) {
            ulonglong2 t = vp[q]; V2[r][2*q] = t.x; V2[r][2*q+1] = t.y;
        }
    }

    const int jb = tid >> 5, cc = tid & 31;
    const float* wbase = Wg + (size_t)jb * NN * 128 + cc * 4;
    const unsigned wdst0 = sm0 + (unsigned)(jb * WJS + cc * 4) * 4;

    #pragma unroll
    for (int q = 0; q < 16; q++) {
        int c = tid + q * TPB;
        int n = c >> 5, b = (c >> 1) & 15, h = c & 1;
        cp16(sm0 + (unsigned)(XOFF + n * (BT1*DD) + b * DD + h * 4) * 4,
             xg + ((size_t)(b0 + b) * NN + (n0 + n)) * DD + h * 4);
    }
    #pragma unroll
    for (int q = 0; q < 8; q++)
        cp16(wdst0 + q * (4*WJS*4),
             wbase + (size_t)n0 * 128 + (size_t)q * 4 * NN * 128);
    cp_commit();
    #pragma unroll
    for (int q = 0; q < 8; q++)
        cp16(wdst0 + (unsigned)(WBUF*4) + q * (4*WJS*4),
             wbase + (size_t)(n0+1) * 128 + (size_t)q * 4 * NN * 128);
    cp_commit();

    u64 s2[4][8];
    #pragma unroll
    for (int r = 0; r < 4; r++)
        #pragma unroll
        for (int q = 0; q < 8; q++) s2[r][q] = 0ull;

    int cur = 0, pf = 2;
    for (int nn = 0; nn < NC1; nn++) {
        if (nn >= NC1 - 2) cp_wait0(); else cp_wait1();
        __syncthreads();
        if (nn + 2 < NC1) {
            unsigned d = wdst0 + (unsigned)(pf * WBUF) * 4;
            const float* s = wbase + (size_t)(n0 + nn + 2) * 128;
            #pragma unroll
            for (int q = 0; q < 8; q++)
                cp16(d + q * (4*WJS*4), s + (size_t)q * 4 * NN * 128);
            cp_commit();
        }

        const float* xrow = sm + XOFF + nn * (BT1*DD);
        u64 X[4][4];
        #pragma unroll
        for (int r = 0; r < 4; r++) {
            const ulonglong2* xp =
                reinterpret_cast<const ulonglong2*>(xrow + (bp + 4*r) * DD);
            ulonglong2 t0 = xp[0], t1 = xp[1];
            X[r][0] = t0.x; X[r][1] = t0.y; X[r][2] = t1.x; X[r][3] = t1.y;
        }

        const float* Wj = sm + cur * WBUF + j * WJS;
        u64 u2[4][8];
        #pragma unroll
        for (int p2 = 0; p2 < 8; p2++) {
            const ulonglong2* wr = reinterpret_cast<const ulonglong2*>(Wj + p2 * 16);
            ulonglong2 w0 = wr[0], w1 = wr[1], w2 = wr[2], w3 = wr[3];
            #pragma unroll
            for (int r = 0; r < 4; r++) {
                u64 a = mul2(w0.x, X[r][0]);
                a = fma2(w0.y, X[r][1], a);
                a = fma2(w1.x, X[r][2], a);
                a = fma2(w1.y, X[r][3], a);
                u64 b = mul2(w2.x, X[r][0]);
                b = fma2(w2.y, X[r][1], b);
                b = fma2(w3.x, X[r][2], b);
                b = fma2(w3.y, X[r][3], b);
                u64 pr; asm("mov.b64 %0, {%1, %2};" : "=l"(pr)
                            : "f"(lohi_add(a)), "f"(lohi_add(b)));
                u2[r][p2] = pr;
            }
        }

        float e[4];
        #pragma unroll
        for (int r = 0; r < 4; r++) {
            u64 la = mul2(V2[r][0], u2[r][0]);
            u64 lb = mul2(V2[r][1], u2[r][1]);
            la = fma2(V2[r][2], u2[r][2], la);
            lb = fma2(V2[r][3], u2[r][3], lb);
            la = fma2(V2[r][4], u2[r][4], la);
            lb = fma2(V2[r][5], u2[r][5], lb);
            la = fma2(V2[r][6], u2[r][6], la);
            lb = fma2(V2[r][7], u2[r][7], lb);
            e[r] = __expf(lohi_add(la) + lohi_add(lb));
        }

        float f[4];
        #pragma unroll
        for (int r = 0; r < 4; r++) {
            float v = e[r];
            v += __shfl_xor_sync(0xffffffffu, v, 4);
            v += __shfl_xor_sync(0xffffffffu, v, 8);
            v += __shfl_xor_sync(0xffffffffu, v, 16);
            f[r] = v;
        }
        if (lane < 4) {
            #pragma unroll
            for (int r = 0; r < 4; r++) e_sh[(lane + 4*r) * 4 + w] = f[r];
        }
        __syncthreads();
        #pragma unroll
        for (int r = 0; r < 4; r++) {
            float4 t = *reinterpret_cast<const float4*>(&e_sh[(bp + 4*r) * 4]);
            float c = e[r] * __frcp_rn((t.x + t.y) + (t.z + t.w));
            u64 c2; asm("mov.b64 %0, {%1, %1};" : "=l"(c2) : "f"(c));
            #pragma unroll
            for (int q = 0; q < 8; q++) s2[r][q] = fma2(c2, u2[r][q], s2[r][q]);
        }

        cur = (cur == 2) ? 0 : cur + 1;
        pf  = (pf  == 2) ? 0 : pf  + 1;
    }

    #pragma unroll
    for (int r = 0; r < 4; r++) {
        ulonglong2* dst = reinterpret_cast<ulonglong2*>(
            &g_part[(((size_t)nt * BB + b0 + bp + 4*r) * JJ + j) * PP]);
        #pragma unroll
        for (int q = 0; q < 4; q++) {
            ulonglong2 t; t.x = s2[r][2*q]; t.y = s2[r][2*q+1]; dst[q] = t;
        }
    }
}

// ============ reduce over nt (k-split 8 + shfl), squash, update V / out ====
__global__ void caps_squash(float* __restrict__ outg, int stage, int nnt)
{
    int t    = blockIdx.x * blockDim.x + threadIdx.x;
    int quad = t & 3;
    int k    = (t >> 2) & 7;            // 8-way nt split
    int vec  = t >> 5;
    if (vec >= BB * JJ) return;

    float4 acc = make_float4(0.f, 0.f, 0.f, 0.f);
    int cnt = nnt >> 3;
    for (int ntk = 0; ntk < cnt; ntk++) {
        int nt = k * cnt + ntk;
        float4 v = *reinterpret_cast<const float4*>(
            &g_part[((size_t)nt * BB * JJ + vec) * PP + quad * 4]);
        acc.x += v.x; acc.y += v.y; acc.z += v.z; acc.w += v.w;
    }
    #pragma unroll
    for (int m = 4; m <= 16; m <<= 1) {
        acc.x += __shfl_xor_sync(0xffffffffu, acc.x, m);
        acc.y += __shfl_xor_sync(0xffffffffu, acc.y, m);
        acc.z += __shfl_xor_sync(0xffffffffu, acc.z, m);
        acc.w += __shfl_xor_sync(0xffffffffu, acc.w, m);
    }

    float s2 = acc.x * acc.x + acc.y * acc.y + acc.z * acc.z + acc.w * acc.w;
    s2 += __shfl_xor_sync(0xffffffffu, s2, 1);
    s2 += __shfl_xor_sync(0xffffffffu, s2, 2);

    float scale = s2 / ((1.0f + s2) * sqrtf(s2 + 1e-7f));
    float4 v4 = make_float4(acc.x * scale, acc.y * scale,
                            acc.z * scale, acc.w * scale);

    if (k == 0) {
        if (stage == 2) {
            *reinterpret_cast<float4*>(&outg[vec * PP + quad * 4]) = v4;
        } else if (stage == 0) {
            *reinterpret_cast<float4*>(&g_V[vec * PP + quad * 4]) = v4;
        } else {
            float4 cur = *reinterpret_cast<const float4*>(&g_V[vec * PP + quad * 4]);
            cur.x += v4.x; cur.y += v4.y; cur.z += v4.z; cur.w += v4.w;
            *reinterpret_cast<float4*>(&g_V[vec * PP + quad * 4]) = cur;
        }
    }
}

extern "C" void kernel_launch(void* const* d_in, const int* in_sizes, int n_in,
                              void* d_out, int out_size)
{
    const float* x = (const float*)d_in[0];
    const float* W = (const float*)d_in[1];
    if (n_in >= 2 && in_sizes[0] > in_sizes[1]) {
        const float* tmp = x; x = W; W = tmp;
    }
    float* out = (float*)d_out;

    cudaFuncSetAttribute(caps_pass0_mma,
        cudaFuncAttributeMaxDynamicSharedMemorySize, SMEM0_B);
    cudaFuncSetAttribute(caps_pass1,
        cudaFuncAttributeMaxDynamicSharedMemorySize, SMEM1_B);

    const int GRID1 = NBT1 * NNT1;                          // 256
    const int SQ_BLOCK = 256;
    const int SQ_GRID  = (BB * JJ * 32 + SQ_BLOCK - 1) / SQ_BLOCK;  // 512

    caps_dummy<<<1, 32>>>();                                // 1 (slot 6 = pass1 #2)
    caps_pass0_mma<<<128, 256, SMEM0_B>>>(x, W);            // 2
    caps_squash<<<SQ_GRID, SQ_BLOCK>>>(out, 0, NNT0);       // 3: V = v0
    caps_pass1<<<GRID1, TPB, SMEM1_B>>>(x, W);              // 4
    caps_squash<<<SQ_GRID, SQ_BLOCK>>>(out, 1, NNT1);       // 5: V += v1
    caps_pass1<<<GRID1, TPB, SMEM1_B>>>(x, W);              // 6 <- profiled
    caps_squash<<<SQ_GRID, SQ_BLOCK>>>(out, 2, NNT1);       // 7: out
}